// round 3
// baseline (speedup 1.0000x reference)
#include <cuda_runtime.h>
#include <math.h>

// Problem constants (fixed shapes from setup_inputs)
#define B_  4
#define T_  8192
#define D_  1024
#define L_  128
#define H_  16
#define HL  8       // L per head
#define HD  64      // D per head
#define M_  (B_*T_) // 32768 tokens

#define KV_CH 16    // T-chunks for KV-state partial reduction
#define MX_CH 32    // T-chunks for K-max partial reduction
#define YTOK  32    // tokens per block in the y kernel

// ---------------- scratch (device globals: allocation-free contract) --------
__device__ float g_Q [M_ * L_];                 // 16.8 MB
__device__ float g_Kr[M_ * L_];                 // 16.8 MB
__device__ float g_V [M_ * D_];                 // 134 MB
__device__ float g_y [M_ * D_];                 // 134 MB
__device__ float g_maxi_part[B_ * MX_CH * L_];
__device__ float g_maxi[B_ * L_];
__device__ float g_Kv_part[B_ * H_ * KV_CH * HL * HD];
__device__ float g_Ks_part[B_ * H_ * KV_CH * HL];
__device__ float g_Kvn[B_ * H_ * HL * HD];

// ---------------- packed f32x2 helpers (FFMA2: 2x fp32 FMA throughput) -----
__device__ __forceinline__ unsigned long long dup2f(float x) {
    unsigned long long r;
    asm("mov.b64 %0, {%1, %1};" : "=l"(r) : "f"(x));
    return r;
}
__device__ __forceinline__ unsigned long long fma2(unsigned long long a,
                                                   unsigned long long b,
                                                   unsigned long long c) {
    unsigned long long d;
    asm("fma.rn.f32x2 %0, %1, %2, %3;" : "=l"(d) : "l"(a), "l"(b), "l"(c));
    return d;
}

// ---------------- 128x128x16 fp32 GEMM, 256 thr, 8x8 per-thread, f32x2 -----
// C[M,N] = A[M,K] @ B[K,N], all row-major, M%128==0, N%128==0, K%16==0
__global__ __launch_bounds__(256, 2)
void sgemm128(const float* __restrict__ A, const float* __restrict__ Bm,
              float* __restrict__ C, int Mdim, int Ndim, int Kdim)
{
    __shared__ float As[16][128];   // transposed A tile: As[k][m]
    __shared__ float Bs[16][128];   // Bs[k][n]

    const int tid = threadIdx.x;
    const int tx  = tid & 15;       // N micro-tile
    const int ty  = tid >> 4;       // M micro-tile
    const long Arow0 = (long)blockIdx.y * 128;
    const int  Bcol0 = blockIdx.x * 128;

    const int aRow = tid >> 2;          // 0..63
    const int aCol = (tid & 3) << 2;    // 0,4,8,12
    const int bRow = tid >> 5;          // 0..7
    const int bCol = (tid & 31) << 2;   // 0..124

    const float* Aptr0 = A + (Arow0 + aRow)      * (long)Kdim + aCol;
    const float* Aptr1 = A + (Arow0 + aRow + 64) * (long)Kdim + aCol;
    const float* Bptr0 = Bm + (long)bRow       * Ndim + Bcol0 + bCol;
    const float* Bptr1 = Bm + (long)(bRow + 8) * Ndim + Bcol0 + bCol;

    // prologue prefetch of tile k0=0
    float4 pa0 = *(const float4*)(Aptr0);
    float4 pa1 = *(const float4*)(Aptr1);
    float4 pb0 = *(const float4*)(Bptr0);
    float4 pb1 = *(const float4*)(Bptr1);

    unsigned long long acc[8][4];
#pragma unroll
    for (int i = 0; i < 8; i++)
#pragma unroll
        for (int j = 0; j < 4; j++) acc[i][j] = 0ULL;

    for (int k0 = 0; k0 < Kdim; k0 += 16) {
        // commit prefetched tile to smem
        As[aCol + 0][aRow]      = pa0.x; As[aCol + 1][aRow]      = pa0.y;
        As[aCol + 2][aRow]      = pa0.z; As[aCol + 3][aRow]      = pa0.w;
        As[aCol + 0][aRow + 64] = pa1.x; As[aCol + 1][aRow + 64] = pa1.y;
        As[aCol + 2][aRow + 64] = pa1.z; As[aCol + 3][aRow + 64] = pa1.w;
        *(float4*)&Bs[bRow][bCol]     = pb0;
        *(float4*)&Bs[bRow + 8][bCol] = pb1;
        __syncthreads();

        if (k0 + 16 < Kdim) {   // prefetch next tile (overlaps with compute)
            pa0 = *(const float4*)(Aptr0 + k0 + 16);
            pa1 = *(const float4*)(Aptr1 + k0 + 16);
            pb0 = *(const float4*)(Bptr0 + (long)(k0 + 16) * Ndim);
            pb1 = *(const float4*)(Bptr1 + (long)(k0 + 16) * Ndim);
        }

#pragma unroll
        for (int kk = 0; kk < 16; kk++) {
            unsigned long long rb[4];
            const unsigned long long* bsrc =
                (const unsigned long long*)&Bs[kk][tx << 3];
            rb[0] = bsrc[0]; rb[1] = bsrc[1]; rb[2] = bsrc[2]; rb[3] = bsrc[3];
#pragma unroll
            for (int i = 0; i < 8; i++) {
                unsigned long long ra = dup2f(As[kk][(ty << 3) + i]);
                acc[i][0] = fma2(ra, rb[0], acc[i][0]);
                acc[i][1] = fma2(ra, rb[1], acc[i][1]);
                acc[i][2] = fma2(ra, rb[2], acc[i][2]);
                acc[i][3] = fma2(ra, rb[3], acc[i][3]);
            }
        }
        __syncthreads();
    }

    float* Cb = C + (Arow0 + (ty << 3)) * (long)Ndim + Bcol0 + (tx << 3);
#pragma unroll
    for (int i = 0; i < 8; i++) {
        float2 u0 = *reinterpret_cast<float2*>(&acc[i][0]);
        float2 u1 = *reinterpret_cast<float2*>(&acc[i][1]);
        float2 u2 = *reinterpret_cast<float2*>(&acc[i][2]);
        float2 u3 = *reinterpret_cast<float2*>(&acc[i][3]);
        *(float4*)(Cb + (long)i * Ndim)     = make_float4(u0.x, u0.y, u1.x, u1.y);
        *(float4*)(Cb + (long)i * Ndim + 4) = make_float4(u2.x, u2.y, u3.x, u3.y);
    }
}

// ---------------- K global max over T: partials then reduce -----------------
__global__ void kmax_part() {
    int b  = blockIdx.x;                 // 0..3
    int ch = blockIdx.y;                 // 0..31
    int c  = threadIdx.x;                // 0..127
    const int CL = T_ / MX_CH;           // 256
    const float* p = g_Kr + ((long)b * T_ + (long)ch * CL) * L_ + c;
    float m = -INFINITY;
    for (int i = 0; i < CL; i++) m = fmaxf(m, p[(long)i * L_]);
    g_maxi_part[(b * MX_CH + ch) * L_ + c] = m;
}
__global__ void kmax_red() {
    int tid = threadIdx.x;               // 0..511
    int b = tid >> 7, c = tid & 127;
    float m = -INFINITY;
    for (int ch = 0; ch < MX_CH; ch++)
        m = fmaxf(m, g_maxi_part[(b * MX_CH + ch) * L_ + c]);
    g_maxi[b * L_ + c] = m;
}

// ---------------- KV state: Kv[b,h,l,d] = sum_t exp(K-max)*m * (V*m) --------
__global__ __launch_bounds__(512)
void kv_part(const float* __restrict__ mask) {
    __shared__ float sKe[8][8];
    __shared__ float sVm[8][64];
    int ch = blockIdx.x;                 // 0..KV_CH-1
    int bh = blockIdx.y;                 // 0..63
    int b = bh >> 4, h = bh & 15;
    int tid = threadIdx.x;               // 512
    int l = tid >> 6, d = tid & 63;
    const int CL = T_ / KV_CH;           // 512
    int t0 = ch * CL;
    float acc = 0.f, ks = 0.f;
    float mx = g_maxi[b * L_ + h * HL + (tid & 7)];   // used by tid<64 loaders

    for (int ts = 0; ts < CL; ts += 8) {
        {   // stage 8 tokens of masked V
            int tt = tid >> 6, dd = tid & 63;
            long m = (long)b * T_ + t0 + ts + tt;
            float mv = mask[m];
            sVm[tt][dd] = g_V[m * (long)D_ + h * HD + dd] * mv;
        }
        if (tid < 64) {  // stage 8 tokens of exp(K-max)*mask
            int tt = tid >> 3, ll = tid & 7;
            long m = (long)b * T_ + t0 + ts + tt;
            float mv = mask[m];
            sKe[tt][ll] = expf(g_Kr[m * (long)L_ + h * HL + ll] - mx) * mv;
        }
        __syncthreads();
#pragma unroll
        for (int tt = 0; tt < 8; tt++) {
            float ke = sKe[tt][l];
            acc += ke * sVm[tt][d];
            if (d == 0) ks += ke;
        }
        __syncthreads();
    }
    g_Kv_part[(((long)bh * KV_CH + ch) * HL + l) * HD + d] = acc;
    if (d == 0) g_Ks_part[((long)bh * KV_CH + ch) * HL + l] = ks;
}

__global__ void kv_red() {
    int bh = blockIdx.x;                 // 0..63
    int tid = threadIdx.x;               // 512
    int l = tid >> 6, d = tid & 63;
    float kv = 0.f, ks = 0.f;
    for (int c = 0; c < KV_CH; c++) {
        kv += g_Kv_part[(((long)bh * KV_CH + c) * HL + l) * HD + d];
        ks += g_Ks_part[((long)bh * KV_CH + c) * HL + l];
    }
    g_Kvn[((long)bh * HL + l) * HD + d] = kv / ks;
}

// ---------------- y[t, h*64+d] = softmax(Q[t,h,:]) @ Kvn[b,h] ---------------
__global__ __launch_bounds__(256)
void y_kern() {
    __shared__ float sKvn[H_ * HL * HD];     // 8192 floats = 32 KB (per batch b)
    __shared__ float sQ[YTOK][L_];           // 16 KB
    int blk = blockIdx.x;                    // 0..1023
    long m0 = (long)blk * YTOK;
    int b = (int)(m0 / T_);                  // block never straddles b (T%YTOK==0)
    int tid = threadIdx.x;

    for (int i = tid; i < H_ * HL * HD; i += 256)
        sKvn[i] = g_Kvn[(long)b * H_ * HL * HD + i];
    for (int idx = tid; idx < YTOK * L_; idx += 256) {
        int i = idx >> 7, c = idx & 127;
        sQ[i][c] = g_Q[(m0 + i) * (long)L_ + c];
    }
    __syncthreads();

    // per-(token, head) softmax over l=8, in place
    for (int task = tid; task < YTOK * H_; task += 256) {
        int i = task >> 4, h = task & 15;
        float* q = &sQ[i][h * HL];
        float mx = q[0];
#pragma unroll
        for (int l = 1; l < 8; l++) mx = fmaxf(mx, q[l]);
        float e[8]; float s = 0.f;
#pragma unroll
        for (int l = 0; l < 8; l++) { e[l] = expf(q[l] - mx); s += e[l]; }
        float inv = 1.f / s;
#pragma unroll
        for (int l = 0; l < 8; l++) q[l] = e[l] * inv;
    }
    __syncthreads();

    for (int i = 0; i < YTOK; i++) {
#pragma unroll
        for (int k = 0; k < 4; k++) {
            int c = tid + k * 256;
            int h = c >> 6, d = c & 63;
            float acc = 0.f;
#pragma unroll
            for (int l = 0; l < 8; l++)
                acc += sQ[i][h * HL + l] * sKvn[(h * HL + l) * HD + d];
            g_y[(m0 + i) * (long)D_ + c] = acc;
        }
    }
}

// ---------------- launch ----------------------------------------------------
extern "C" void kernel_launch(void* const* d_in, const int* in_sizes, int n_in,
                              void* d_out, int out_size)
{
    const float* X    = (const float*)d_in[0];
    const float* mask = (const float*)d_in[1];
    const float* Wk   = (const float*)d_in[2];
    const float* Wq   = (const float*)d_in[3];
    const float* Wv   = (const float*)d_in[4];
    const float* Wo   = (const float*)d_in[5];
    float* out = (float*)d_out;
    (void)in_sizes; (void)n_in; (void)out_size;

    float *pQ, *pK, *pV, *py;
    cudaGetSymbolAddress((void**)&pQ, g_Q);
    cudaGetSymbolAddress((void**)&pK, g_Kr);
    cudaGetSymbolAddress((void**)&pV, g_V);
    cudaGetSymbolAddress((void**)&py, g_y);

    dim3 thr(256);
    // projections
    sgemm128<<<dim3(L_ / 128, M_ / 128), thr>>>(X, Wq, pQ, M_, L_, D_);
    sgemm128<<<dim3(L_ / 128, M_ / 128), thr>>>(X, Wk, pK, M_, L_, D_);
    sgemm128<<<dim3(D_ / 128, M_ / 128), thr>>>(X, Wv, pV, M_, D_, D_);
    // global K max over T
    kmax_part<<<dim3(B_, MX_CH), 128>>>();
    kmax_red<<<1, 512>>>();
    // KV state + normalizer
    kv_part<<<dim3(KV_CH, B_ * H_), 512>>>(mask);
    kv_red<<<B_ * H_, 512>>>();
    // attention read-out
    y_kern<<<M_ / YTOK, 256>>>();
    // output projection
    sgemm128<<<dim3(D_ / 128, M_ / 128), thr>>>(py, Wo, out, M_, D_, D_);
}

// round 4
// speedup vs baseline: 2.3540x; 2.3540x over previous
#include <cuda_runtime.h>
#include <math.h>
#include <stdint.h>

// Problem constants (fixed shapes from setup_inputs)
#define B_  4
#define T_  8192
#define D_  1024
#define L_  128
#define H_  16
#define HL  8       // L per head
#define HD  64      // D per head
#define M_  (B_*T_) // 32768 tokens

#define KV_CH 16
#define MX_CH 32
#define YTOK  32

// ---------------- scratch (device globals: allocation-free contract) --------
__device__ float g_Q [M_ * L_];
__device__ float g_Kr[M_ * L_];
__device__ float g_V [M_ * D_];
__device__ float g_y [M_ * D_];
__device__ float g_maxi_part[B_ * MX_CH * L_];
__device__ float g_maxi[B_ * L_];
__device__ float g_Kv_part[B_ * H_ * KV_CH * HL * HD];
__device__ float g_Ks_part[B_ * H_ * KV_CH * HL];
__device__ float g_Kvn[B_ * H_ * HL * HD];

// ---------------- tf32 helpers ----------------------------------------------
__device__ __forceinline__ uint32_t f2tf(float x) {
    uint32_t r; asm("cvt.rna.tf32.f32 %0, %1;" : "=r"(r) : "f"(x)); return r;
}

__device__ __forceinline__ void mma_tf32(float* d, const uint32_t* a, const uint32_t* b) {
    asm volatile(
      "mma.sync.aligned.m16n8k8.row.col.f32.tf32.tf32.f32 "
      "{%0,%1,%2,%3}, {%4,%5,%6,%7}, {%8,%9}, {%0,%1,%2,%3};\n"
      : "+f"(d[0]), "+f"(d[1]), "+f"(d[2]), "+f"(d[3])
      : "r"(a[0]), "r"(a[1]), "r"(a[2]), "r"(a[3]), "r"(b[0]), "r"(b[1]));
}

// smem pitch 20 floats: 20 ≡ 4 (mod 32) -> fragment reads are a bank permutation
#define AP 20
#define BP 20

// ---------------- tf32 tensor-core GEMM: C[M,N] = A[M,K] @ B[K,N] -----------
// 128x128 block tile, BK=16, 256 threads, 8 warps as 2(m)x4(n), warp tile 64x32.
__global__ __launch_bounds__(256)
void gemm_tf32(const float* __restrict__ A, const float* __restrict__ Bm,
               float* __restrict__ C, int Ndim, int Kdim)
{
    __shared__ uint32_t As[2][128 * AP];   // As[buf][m*AP + k], k in [0,16)
    __shared__ uint32_t Bs[2][128 * BP];   // Bs[buf][n*BP + k]  (B^T tile)

    const int tid  = threadIdx.x;
    const int lane = tid & 31;
    const int wid  = tid >> 5;
    const int wm   = wid & 1;        // m offset wm*64
    const int wn   = wid >> 1;       // n offset wn*32
    const long Arow0 = (long)blockIdx.y * 128;
    const int  Bcol0 = blockIdx.x * 128;

    // global->smem mapping
    const int aRow = tid >> 1;                // 0..127
    const int aKh  = (tid & 1) << 3;          // 0 or 8
    const int bN   = tid & 127;               // 0..127
    const int bKq  = (tid >> 7) << 3;         // 0 or 8

    const float* pA = A + (Arow0 + aRow) * (long)Kdim + aKh;
    const float* pB = Bm + Bcol0 + bN;

    float4 ra0, ra1;
    float  rb[8];

    // prologue: load tile 0
    ra0 = *(const float4*)(pA);
    ra1 = *(const float4*)(pA + 4);
#pragma unroll
    for (int j = 0; j < 8; j++) rb[j] = pB[(long)(bKq + j) * Ndim];

    {   // commit tile 0 to buffer 0 (convert to tf32 on the way)
        uint32_t* as = &As[0][aRow * AP + aKh];
        *(uint4*)(as)     = make_uint4(f2tf(ra0.x), f2tf(ra0.y), f2tf(ra0.z), f2tf(ra0.w));
        *(uint4*)(as + 4) = make_uint4(f2tf(ra1.x), f2tf(ra1.y), f2tf(ra1.z), f2tf(ra1.w));
        uint32_t* bs = &Bs[0][bN * BP + bKq];
        *(uint4*)(bs)     = make_uint4(f2tf(rb[0]), f2tf(rb[1]), f2tf(rb[2]), f2tf(rb[3]));
        *(uint4*)(bs + 4) = make_uint4(f2tf(rb[4]), f2tf(rb[5]), f2tf(rb[6]), f2tf(rb[7]));
    }
    __syncthreads();

    float acc[4][4][4];
#pragma unroll
    for (int i = 0; i < 4; i++)
#pragma unroll
        for (int j = 0; j < 4; j++)
#pragma unroll
            for (int v = 0; v < 4; v++) acc[i][j][v] = 0.f;

    const int ntile = Kdim >> 4;
    const int r4 = lane >> 2, c4 = lane & 3;

    for (int kt = 0; kt < ntile; kt++) {
        if (kt + 1 < ntile) {   // prefetch next tile into registers
            const float* qA = pA + (kt + 1) * 16;
            ra0 = *(const float4*)(qA);
            ra1 = *(const float4*)(qA + 4);
            const float* qB = pB + (long)((kt + 1) * 16 + bKq) * Ndim;
#pragma unroll
            for (int j = 0; j < 8; j++) rb[j] = qB[(long)j * Ndim];
        }

        const uint32_t* as = As[kt & 1];
        const uint32_t* bs = Bs[kt & 1];
#pragma unroll
        for (int k8 = 0; k8 < 2; k8++) {
            const int kb = k8 << 3;
            uint32_t afrag[4][4], bfrag[4][2];
#pragma unroll
            for (int mt = 0; mt < 4; mt++) {
                const int m0 = wm * 64 + mt * 16 + r4;
                afrag[mt][0] = as[(m0    ) * AP + kb + c4];
                afrag[mt][1] = as[(m0 + 8) * AP + kb + c4];
                afrag[mt][2] = as[(m0    ) * AP + kb + c4 + 4];
                afrag[mt][3] = as[(m0 + 8) * AP + kb + c4 + 4];
            }
#pragma unroll
            for (int nt = 0; nt < 4; nt++) {
                const int n0 = wn * 32 + nt * 8 + r4;
                bfrag[nt][0] = bs[n0 * BP + kb + c4];
                bfrag[nt][1] = bs[n0 * BP + kb + c4 + 4];
            }
#pragma unroll
            for (int mt = 0; mt < 4; mt++)
#pragma unroll
                for (int nt = 0; nt < 4; nt++)
                    mma_tf32(acc[mt][nt], afrag[mt], bfrag[nt]);
        }

        if (kt + 1 < ntile) {   // commit prefetched tile to other buffer
            uint32_t* asw = &As[(kt + 1) & 1][aRow * AP + aKh];
            *(uint4*)(asw)     = make_uint4(f2tf(ra0.x), f2tf(ra0.y), f2tf(ra0.z), f2tf(ra0.w));
            *(uint4*)(asw + 4) = make_uint4(f2tf(ra1.x), f2tf(ra1.y), f2tf(ra1.z), f2tf(ra1.w));
            uint32_t* bsw = &Bs[(kt + 1) & 1][bN * BP + bKq];
            *(uint4*)(bsw)     = make_uint4(f2tf(rb[0]), f2tf(rb[1]), f2tf(rb[2]), f2tf(rb[3]));
            *(uint4*)(bsw + 4) = make_uint4(f2tf(rb[4]), f2tf(rb[5]), f2tf(rb[6]), f2tf(rb[7]));
        }
        __syncthreads();
    }

    // epilogue
    float* Cb = C + (Arow0 + wm * 64) * (long)Ndim + Bcol0 + wn * 32;
#pragma unroll
    for (int mt = 0; mt < 4; mt++) {
        const int r = mt * 16 + r4;
#pragma unroll
        for (int nt = 0; nt < 4; nt++) {
            const int c = nt * 8 + c4 * 2;
            *(float2*)(Cb + (long)r * Ndim + c)       = make_float2(acc[mt][nt][0], acc[mt][nt][1]);
            *(float2*)(Cb + (long)(r + 8) * Ndim + c) = make_float2(acc[mt][nt][2], acc[mt][nt][3]);
        }
    }
}

// ---------------- K global max over T: partials then reduce -----------------
__global__ void kmax_part() {
    int b  = blockIdx.x;
    int ch = blockIdx.y;
    int c  = threadIdx.x;
    const int CL = T_ / MX_CH;
    const float* p = g_Kr + ((long)b * T_ + (long)ch * CL) * L_ + c;
    float m = -INFINITY;
    for (int i = 0; i < CL; i++) m = fmaxf(m, p[(long)i * L_]);
    g_maxi_part[(b * MX_CH + ch) * L_ + c] = m;
}
__global__ void kmax_red() {
    int tid = threadIdx.x;
    int b = tid >> 7, c = tid & 127;
    float m = -INFINITY;
    for (int ch = 0; ch < MX_CH; ch++)
        m = fmaxf(m, g_maxi_part[(b * MX_CH + ch) * L_ + c]);
    g_maxi[b * L_ + c] = m;
}

// ---------------- KV state: Kv[b,h,l,d] = sum_t exp(K-max)*m * (V*m) --------
__global__ __launch_bounds__(512)
void kv_part(const float* __restrict__ mask) {
    __shared__ float sKe[8][8];
    __shared__ float sVm[8][64];
    int ch = blockIdx.x;
    int bh = blockIdx.y;
    int b = bh >> 4, h = bh & 15;
    int tid = threadIdx.x;
    int l = tid >> 6, d = tid & 63;
    const int CL = T_ / KV_CH;
    int t0 = ch * CL;
    float acc = 0.f, ks = 0.f;
    float mx = g_maxi[b * L_ + h * HL + (tid & 7)];

    for (int ts = 0; ts < CL; ts += 8) {
        {
            int tt = tid >> 6, dd = tid & 63;
            long m = (long)b * T_ + t0 + ts + tt;
            float mv = mask[m];
            sVm[tt][dd] = g_V[m * (long)D_ + h * HD + dd] * mv;
        }
        if (tid < 64) {
            int tt = tid >> 3, ll = tid & 7;
            long m = (long)b * T_ + t0 + ts + tt;
            float mv = mask[m];
            sKe[tt][ll] = expf(g_Kr[m * (long)L_ + h * HL + ll] - mx) * mv;
        }
        __syncthreads();
#pragma unroll
        for (int tt = 0; tt < 8; tt++) {
            float ke = sKe[tt][l];
            acc += ke * sVm[tt][d];
            if (d == 0) ks += ke;
        }
        __syncthreads();
    }
    g_Kv_part[(((long)bh * KV_CH + ch) * HL + l) * HD + d] = acc;
    if (d == 0) g_Ks_part[((long)bh * KV_CH + ch) * HL + l] = ks;
}

__global__ void kv_red() {
    int bh = blockIdx.x;
    int tid = threadIdx.x;
    int l = tid >> 6, d = tid & 63;
    float kv = 0.f, ks = 0.f;
    for (int c = 0; c < KV_CH; c++) {
        kv += g_Kv_part[(((long)bh * KV_CH + c) * HL + l) * HD + d];
        ks += g_Ks_part[((long)bh * KV_CH + c) * HL + l];
    }
    g_Kvn[((long)bh * HL + l) * HD + d] = kv / ks;
}

// ---------------- y[t, h*64+d] = softmax(Q[t,h,:]) @ Kvn[b,h] ---------------
__global__ __launch_bounds__(256)
void y_kern() {
    __shared__ float sKvn[H_ * HL * HD];
    __shared__ float sQ[YTOK][L_];
    int blk = blockIdx.x;
    long m0 = (long)blk * YTOK;
    int b = (int)(m0 / T_);
    int tid = threadIdx.x;

    for (int i = tid; i < H_ * HL * HD; i += 256)
        sKvn[i] = g_Kvn[(long)b * H_ * HL * HD + i];
    for (int idx = tid; idx < YTOK * L_; idx += 256) {
        int i = idx >> 7, c = idx & 127;
        sQ[i][c] = g_Q[(m0 + i) * (long)L_ + c];
    }
    __syncthreads();

    for (int task = tid; task < YTOK * H_; task += 256) {
        int i = task >> 4, h = task & 15;
        float* q = &sQ[i][h * HL];
        float mx = q[0];
#pragma unroll
        for (int l = 1; l < 8; l++) mx = fmaxf(mx, q[l]);
        float e[8]; float s = 0.f;
#pragma unroll
        for (int l = 0; l < 8; l++) { e[l] = expf(q[l] - mx); s += e[l]; }
        float inv = 1.f / s;
#pragma unroll
        for (int l = 0; l < 8; l++) q[l] = e[l] * inv;
    }
    __syncthreads();

    for (int i = 0; i < YTOK; i++) {
#pragma unroll
        for (int k = 0; k < 4; k++) {
            int c = tid + k * 256;
            int h = c >> 6, d = c & 63;
            float acc = 0.f;
#pragma unroll
            for (int l = 0; l < 8; l++)
                acc += sQ[i][h * HL + l] * sKvn[(h * HL + l) * HD + d];
            g_y[(m0 + i) * (long)D_ + c] = acc;
        }
    }
}

// ---------------- launch ----------------------------------------------------
extern "C" void kernel_launch(void* const* d_in, const int* in_sizes, int n_in,
                              void* d_out, int out_size)
{
    const float* X    = (const float*)d_in[0];
    const float* mask = (const float*)d_in[1];
    const float* Wk   = (const float*)d_in[2];
    const float* Wq   = (const float*)d_in[3];
    const float* Wv   = (const float*)d_in[4];
    const float* Wo   = (const float*)d_in[5];
    float* out = (float*)d_out;
    (void)in_sizes; (void)n_in; (void)out_size;

    float *pQ, *pK, *pV, *py;
    cudaGetSymbolAddress((void**)&pQ, g_Q);
    cudaGetSymbolAddress((void**)&pK, g_Kr);
    cudaGetSymbolAddress((void**)&pV, g_V);
    cudaGetSymbolAddress((void**)&py, g_y);

    dim3 thr(256);
    // projections (tf32 tensor cores)
    gemm_tf32<<<dim3(L_ / 128, M_ / 128), thr>>>(X, Wq, pQ, L_, D_);
    gemm_tf32<<<dim3(L_ / 128, M_ / 128), thr>>>(X, Wk, pK, L_, D_);
    gemm_tf32<<<dim3(D_ / 128, M_ / 128), thr>>>(X, Wv, pV, D_, D_);
    // global K max over T
    kmax_part<<<dim3(B_, MX_CH), 128>>>();
    kmax_red<<<1, 512>>>();
    // KV state + normalizer
    kv_part<<<dim3(KV_CH, B_ * H_), 512>>>(mask);
    kv_red<<<B_ * H_, 512>>>();
    // attention read-out
    y_kern<<<M_ / YTOK, 256>>>();
    // output projection
    gemm_tf32<<<dim3(D_ / 128, M_ / 128), thr>>>(py, Wo, out, D_, D_);
}

// round 5
// speedup vs baseline: 6.0119x; 2.5539x over previous
#include <cuda_runtime.h>
#include <math.h>
#include <stdint.h>

#define B_  4
#define T_  8192
#define D_  1024
#define L_  128
#define H_  16
#define HL  8
#define HD  64
#define M_  (B_*T_)

#define MX_CH 32
#define S_CH  16     // split-K chunks for S = Ke^T @ X   (T/512)
#define KE_CH 64     // token chunks for ke_kern partial Ksum

// ---------------- scratch ----------------------------------------------------
__device__ __align__(256) float g_Q  [M_ * L_];
__device__ __align__(256) float g_Kr [M_ * L_];
__device__ __align__(256) float g_Ke [M_ * L_];
__device__ __align__(256) float g_Qs [M_ * L_];
__device__ __align__(256) float g_Sp [S_CH * B_ * L_ * D_];   // split-K partials
__device__ __align__(256) float g_Wc [B_ * L_ * D_];          // Wcomb
__device__ __align__(256) float g_maxi_part[B_ * MX_CH * L_];
__device__ __align__(256) float g_maxi[B_ * L_];
__device__ __align__(256) float g_Kes_part[B_ * KE_CH * L_];
__device__ __align__(256) float g_Ksum[B_ * L_];
__device__ __align__(256) float g_Kvn[B_ * H_ * HL * HD];

// ---------------- tf32 helpers -----------------------------------------------
__device__ __forceinline__ uint32_t f2tf(float x) {
    uint32_t r; asm("cvt.rna.tf32.f32 %0, %1;" : "=r"(r) : "f"(x)); return r;
}
__device__ __forceinline__ void mma_tf32(float* d, const uint32_t* a, const uint32_t* b) {
    asm volatile(
      "mma.sync.aligned.m16n8k8.row.col.f32.tf32.tf32.f32 "
      "{%0,%1,%2,%3}, {%4,%5,%6,%7}, {%8,%9}, {%0,%1,%2,%3};\n"
      : "+f"(d[0]), "+f"(d[1]), "+f"(d[2]), "+f"(d[3])
      : "r"(a[0]), "r"(a[1]), "r"(a[2]), "r"(a[3]), "r"(b[0]), "r"(b[1]));
}
#define AP 20
#define BP 20

// ---------------- core: 128x128 tile, A row-major [M,K], B row-major [K,N] ---
__device__ __forceinline__ void gemm128_core(
    const float* __restrict__ A, const float* __restrict__ Bm,
    float* __restrict__ C, int NdimB, int NdimC, int Kdim,
    long Arow0, int Bcol0)
{
    __shared__ uint32_t As[2][128 * AP];
    __shared__ uint32_t Bs[2][128 * BP];

    const int tid  = threadIdx.x;
    const int lane = tid & 31;
    const int wid  = tid >> 5;
    const int wm   = wid & 1;
    const int wn   = wid >> 1;

    const int aRow = tid >> 1;
    const int aKh  = (tid & 1) << 3;
    const int bN   = tid & 127;
    const int bKq  = (tid >> 7) << 3;

    const float* pA = A + (Arow0 + aRow) * (long)Kdim + aKh;
    const float* pB = Bm + Bcol0 + bN;

    float4 ra0, ra1;
    float  rb[8];

    ra0 = *(const float4*)(pA);
    ra1 = *(const float4*)(pA + 4);
#pragma unroll
    for (int j = 0; j < 8; j++) rb[j] = pB[(long)(bKq + j) * NdimB];

    {
        uint32_t* as = &As[0][aRow * AP + aKh];
        *(uint4*)(as)     = make_uint4(f2tf(ra0.x), f2tf(ra0.y), f2tf(ra0.z), f2tf(ra0.w));
        *(uint4*)(as + 4) = make_uint4(f2tf(ra1.x), f2tf(ra1.y), f2tf(ra1.z), f2tf(ra1.w));
        uint32_t* bs = &Bs[0][bN * BP + bKq];
        *(uint4*)(bs)     = make_uint4(f2tf(rb[0]), f2tf(rb[1]), f2tf(rb[2]), f2tf(rb[3]));
        *(uint4*)(bs + 4) = make_uint4(f2tf(rb[4]), f2tf(rb[5]), f2tf(rb[6]), f2tf(rb[7]));
    }
    __syncthreads();

    float acc[4][4][4];
#pragma unroll
    for (int i = 0; i < 4; i++)
#pragma unroll
        for (int j = 0; j < 4; j++)
#pragma unroll
            for (int v = 0; v < 4; v++) acc[i][j][v] = 0.f;

    const int ntile = Kdim >> 4;
    const int r4 = lane >> 2, c4 = lane & 3;

    for (int kt = 0; kt < ntile; kt++) {
        if (kt + 1 < ntile) {
            const float* qA = pA + (kt + 1) * 16;
            ra0 = *(const float4*)(qA);
            ra1 = *(const float4*)(qA + 4);
            const float* qB = pB + (long)((kt + 1) * 16 + bKq) * NdimB;
#pragma unroll
            for (int j = 0; j < 8; j++) rb[j] = qB[(long)j * NdimB];
        }
        const uint32_t* as = As[kt & 1];
        const uint32_t* bs = Bs[kt & 1];
#pragma unroll
        for (int k8 = 0; k8 < 2; k8++) {
            const int kb = k8 << 3;
            uint32_t afrag[4][4], bfrag[4][2];
#pragma unroll
            for (int mt = 0; mt < 4; mt++) {
                const int m0 = wm * 64 + mt * 16 + r4;
                afrag[mt][0] = as[(m0    ) * AP + kb + c4];
                afrag[mt][1] = as[(m0 + 8) * AP + kb + c4];
                afrag[mt][2] = as[(m0    ) * AP + kb + c4 + 4];
                afrag[mt][3] = as[(m0 + 8) * AP + kb + c4 + 4];
            }
#pragma unroll
            for (int nt = 0; nt < 4; nt++) {
                const int n0 = wn * 32 + nt * 8 + r4;
                bfrag[nt][0] = bs[n0 * BP + kb + c4];
                bfrag[nt][1] = bs[n0 * BP + kb + c4 + 4];
            }
#pragma unroll
            for (int mt = 0; mt < 4; mt++)
#pragma unroll
                for (int nt = 0; nt < 4; nt++)
                    mma_tf32(acc[mt][nt], afrag[mt], bfrag[nt]);
        }
        if (kt + 1 < ntile) {
            uint32_t* asw = &As[(kt + 1) & 1][aRow * AP + aKh];
            *(uint4*)(asw)     = make_uint4(f2tf(ra0.x), f2tf(ra0.y), f2tf(ra0.z), f2tf(ra0.w));
            *(uint4*)(asw + 4) = make_uint4(f2tf(ra1.x), f2tf(ra1.y), f2tf(ra1.z), f2tf(ra1.w));
            uint32_t* bsw = &Bs[(kt + 1) & 1][bN * BP + bKq];
            *(uint4*)(bsw)     = make_uint4(f2tf(rb[0]), f2tf(rb[1]), f2tf(rb[2]), f2tf(rb[3]));
            *(uint4*)(bsw + 4) = make_uint4(f2tf(rb[4]), f2tf(rb[5]), f2tf(rb[6]), f2tf(rb[7]));
        }
        __syncthreads();
    }

    float* Cb = C + (Arow0 + wm * 64) * (long)NdimC + Bcol0 + wn * 32;
#pragma unroll
    for (int mt = 0; mt < 4; mt++) {
        const int r = mt * 16 + r4;
#pragma unroll
        for (int nt = 0; nt < 4; nt++) {
            const int c = nt * 8 + c4 * 2;
            *(float2*)(Cb + (long)r * NdimC + c)       = make_float2(acc[mt][nt][0], acc[mt][nt][1]);
            *(float2*)(Cb + (long)(r + 8) * NdimC + c) = make_float2(acc[mt][nt][2], acc[mt][nt][3]);
        }
    }
}

// Q and K projections fused: one read of X, two weight mats
__global__ __launch_bounds__(256)
void qk_gemm(const float* __restrict__ X, const float* __restrict__ Wq,
             const float* __restrict__ Wk)
{
    long Arow0 = (long)blockIdx.y * 128;
    if (blockIdx.x == 0)
        gemm128_core(X, Wq, g_Q,  L_, L_, D_, Arow0, 0);
    else
        gemm128_core(X, Wk, g_Kr, L_, L_, D_, Arow0, 0);
}

// out[b*T+t, :] = Qs[t,:] @ Wcomb[b]   (K=128, per-batch B)
__global__ __launch_bounds__(256)
void out_gemm(float* __restrict__ out)
{
    long Arow0 = (long)blockIdx.y * 128;
    int b = (int)(Arow0 >> 13);           // 8192 rows per batch
    gemm128_core(g_Qs, g_Wc + (long)b * L_ * D_, out, D_, D_, L_,
                 Arow0, blockIdx.x * 128);
}

// ---------------- S = Ke^T @ X  (TN, split-K over T) -------------------------
// S_part[c][b][l][n] = sum_{t in chunk} Ke[b*T+t, l] * X[b*T+t, n]
__global__ __launch_bounds__(256)
void s_gemm(const float* __restrict__ X)
{
    const int bx = blockIdx.x;       // n block 0..7
    const int c  = blockIdx.y;       // chunk 0..15
    const int b  = blockIdx.z;
    const float* A  = g_Ke + ((long)b * T_ + c * 512) * L_;
    const float* Bp = X    + ((long)b * T_ + c * 512) * D_ + bx * 128;

    __shared__ uint32_t As[2][128 * AP];
    __shared__ uint32_t Bs[2][128 * BP];

    const int tid  = threadIdx.x;
    const int lane = tid & 31;
    const int wid  = tid >> 5;
    const int wm   = wid & 1;
    const int wn   = wid >> 1;
    const int col  = tid & 127;
    const int kq   = (tid >> 7) << 3;

    float ra[8], rb[8];
#pragma unroll
    for (int j = 0; j < 8; j++) {
        ra[j] = A [(long)(kq + j) * L_ + col];
        rb[j] = Bp[(long)(kq + j) * D_ + col];
    }
    {
        uint32_t* as = &As[0][col * AP + kq];
        uint32_t* bs = &Bs[0][col * BP + kq];
#pragma unroll
        for (int j = 0; j < 8; j++) { as[j] = f2tf(ra[j]); bs[j] = f2tf(rb[j]); }
    }
    __syncthreads();

    float acc[4][4][4];
#pragma unroll
    for (int i = 0; i < 4; i++)
#pragma unroll
        for (int j = 0; j < 4; j++)
#pragma unroll
            for (int v = 0; v < 4; v++) acc[i][j][v] = 0.f;

    const int ntile = 512 >> 4;           // 32
    const int r4 = lane >> 2, c4 = lane & 3;

    for (int kt = 0; kt < ntile; kt++) {
        if (kt + 1 < ntile) {
            const float* qA = A  + (long)((kt + 1) * 16 + kq) * L_ + col;
            const float* qB = Bp + (long)((kt + 1) * 16 + kq) * D_ + col;
#pragma unroll
            for (int j = 0; j < 8; j++) { ra[j] = qA[(long)j * L_]; rb[j] = qB[(long)j * D_]; }
        }
        const uint32_t* as = As[kt & 1];
        const uint32_t* bs = Bs[kt & 1];
#pragma unroll
        for (int k8 = 0; k8 < 2; k8++) {
            const int kb = k8 << 3;
            uint32_t afrag[4][4], bfrag[4][2];
#pragma unroll
            for (int mt = 0; mt < 4; mt++) {
                const int m0 = wm * 64 + mt * 16 + r4;
                afrag[mt][0] = as[(m0    ) * AP + kb + c4];
                afrag[mt][1] = as[(m0 + 8) * AP + kb + c4];
                afrag[mt][2] = as[(m0    ) * AP + kb + c4 + 4];
                afrag[mt][3] = as[(m0 + 8) * AP + kb + c4 + 4];
            }
#pragma unroll
            for (int nt = 0; nt < 4; nt++) {
                const int n0 = wn * 32 + nt * 8 + r4;
                bfrag[nt][0] = bs[n0 * BP + kb + c4];
                bfrag[nt][1] = bs[n0 * BP + kb + c4 + 4];
            }
#pragma unroll
            for (int mt = 0; mt < 4; mt++)
#pragma unroll
                for (int nt = 0; nt < 4; nt++)
                    mma_tf32(acc[mt][nt], afrag[mt], bfrag[nt]);
        }
        if (kt + 1 < ntile) {
            uint32_t* asw = &As[(kt + 1) & 1][col * AP + kq];
            uint32_t* bsw = &Bs[(kt + 1) & 1][col * BP + kq];
#pragma unroll
            for (int j = 0; j < 8; j++) { asw[j] = f2tf(ra[j]); bsw[j] = f2tf(rb[j]); }
        }
        __syncthreads();
    }

    float* Cb = g_Sp + (((long)c * B_ + b) * L_ + wm * 64) * D_ + bx * 128 + wn * 32;
#pragma unroll
    for (int mt = 0; mt < 4; mt++) {
        const int r = mt * 16 + r4;
#pragma unroll
        for (int nt = 0; nt < 4; nt++) {
            const int cc = nt * 8 + c4 * 2;
            *(float2*)(Cb + (long)r * D_ + cc)       = make_float2(acc[mt][nt][0], acc[mt][nt][1]);
            *(float2*)(Cb + (long)(r + 8) * D_ + cc) = make_float2(acc[mt][nt][2], acc[mt][nt][3]);
        }
    }
}

// ---------------- K global max ----------------------------------------------
__global__ void kmax_part() {
    int b  = blockIdx.x, ch = blockIdx.y, c = threadIdx.x;
    const int CL = T_ / MX_CH;
    const float* p = g_Kr + ((long)b * T_ + (long)ch * CL) * L_ + c;
    float m = -INFINITY;
    for (int i = 0; i < CL; i++) m = fmaxf(m, p[(long)i * L_]);
    g_maxi_part[(b * MX_CH + ch) * L_ + c] = m;
}
__global__ void kmax_red() {
    int tid = threadIdx.x;
    int b = tid >> 7, c = tid & 127;
    float m = -INFINITY;
    for (int ch = 0; ch < MX_CH; ch++)
        m = fmaxf(m, g_maxi_part[(b * MX_CH + ch) * L_ + c]);
    g_maxi[b * L_ + c] = m;
}

// ---------------- Ke = exp(K-max)*m*m  (m^2 for the Kv path), partial Ksum --
__global__ __launch_bounds__(256)
void ke_kern(const float* __restrict__ mask) {
    __shared__ float red[256];
    int ch = blockIdx.x, b = blockIdx.y;
    int tid = threadIdx.x;
    int l = tid & 127, half = tid >> 7;
    long t0 = (long)b * T_ + ch * 128 + half * 64;
    float mx = g_maxi[b * L_ + l];
    float s = 0.f;
    for (int i = 0; i < 64; i++) {
        long t = t0 + i;
        float mv = mask[t];
        float e = expf(g_Kr[t * L_ + l] - mx);
        s += e * mv;                       // Ksum uses single m
        g_Ke[t * L_ + l] = e * mv * mv;    // GEMM operand carries m^2
    }
    red[tid] = s;
    __syncthreads();
    if (half == 0)
        g_Kes_part[(b * KE_CH + ch) * L_ + l] = red[l] + red[128 + l];
}
__global__ void ks_red() {
    int tid = threadIdx.x;                // 512
    int b = tid >> 7, l = tid & 127;
    float s = 0.f;
    for (int c = 0; c < KE_CH; c++) s += g_Kes_part[(b * KE_CH + c) * L_ + l];
    g_Ksum[b * L_ + l] = s;
}

// ---------------- Kvn[b,h,l,d] = (sum_c Sp)[h*8+l,:] @ Wv[:, h*64+d] / Ksum --
__global__ __launch_bounds__(512)
void kv_small(const float* __restrict__ Wv) {
    __shared__ float sS[HL * D_];         // 32 KB
    int bh = blockIdx.x;
    int b = bh >> 4, h = bh & 15;
    int tid = threadIdx.x;
    for (int idx = tid; idx < HL * D_; idx += 512) {
        int l = idx >> 10, p = idx & 1023;
        float v = 0.f;
#pragma unroll
        for (int c = 0; c < S_CH; c++)
            v += g_Sp[(((long)c * B_ + b) * L_ + h * HL + l) * D_ + p];
        sS[idx] = v;
    }
    __syncthreads();
    int l = tid >> 6, d = tid & 63;
    float acc = 0.f;
    const float* wv = Wv + h * HD + d;
#pragma unroll 8
    for (int p = 0; p < D_; p++)
        acc += sS[l * D_ + p] * wv[(long)p * D_];
    float ks = g_Ksum[b * L_ + h * HL + l];
    g_Kvn[((long)bh * HL + l) * HD + d] = acc / ks;
}

// ---------------- Wcomb[b][h*8+l, n] = sum_d Kvn[b,h,l,d]*Wo[h*64+d, n] ------
__global__ __launch_bounds__(256)
void wcomb_kern(const float* __restrict__ Wo) {
    __shared__ float sKvn[L_ * HD / 2 * 2];   // 128*64 = 8192 floats (32 KB)
    int b = blockIdx.x, nb = blockIdx.y;
    int tid = threadIdx.x;
    for (int i = tid; i < H_ * HL * HD; i += 256)
        sKvn[i] = g_Kvn[(long)b * H_ * HL * HD + i];
    __syncthreads();
    int c = tid & 127, hhalf = tid >> 7;
    int col = nb * 128 + c;
#pragma unroll
    for (int hh = 0; hh < 8; hh++) {
        int h = hhalf * 8 + hh;
        float a8[8];
#pragma unroll
        for (int l = 0; l < 8; l++) a8[l] = 0.f;
        for (int d = 0; d < HD; d++) {
            float w = Wo[(long)(h * HD + d) * D_ + col];
#pragma unroll
            for (int l = 0; l < 8; l++)
                a8[l] += sKvn[(h * HL + l) * HD + d] * w;
        }
#pragma unroll
        for (int l = 0; l < 8; l++)
            g_Wc[((long)b * L_ + h * HL + l) * D_ + col] = a8[l];
    }
}

// ---------------- softmax over l=8 per (token, head) -------------------------
__global__ __launch_bounds__(256)
void softmax_q() {
    long idx = (long)blockIdx.x * 256 + threadIdx.x;   // (token, head) pair
    long off = idx * HL;                               // 8 contiguous floats
    float4 q0 = *(const float4*)(g_Q + off);
    float4 q1 = *(const float4*)(g_Q + off + 4);
    float mx = fmaxf(fmaxf(fmaxf(q0.x, q0.y), fmaxf(q0.z, q0.w)),
                     fmaxf(fmaxf(q1.x, q1.y), fmaxf(q1.z, q1.w)));
    float e0 = expf(q0.x - mx), e1 = expf(q0.y - mx), e2 = expf(q0.z - mx), e3 = expf(q0.w - mx);
    float e4 = expf(q1.x - mx), e5 = expf(q1.y - mx), e6 = expf(q1.z - mx), e7 = expf(q1.w - mx);
    float inv = 1.f / (e0 + e1 + e2 + e3 + e4 + e5 + e6 + e7);
    *(float4*)(g_Qs + off)     = make_float4(e0 * inv, e1 * inv, e2 * inv, e3 * inv);
    *(float4*)(g_Qs + off + 4) = make_float4(e4 * inv, e5 * inv, e6 * inv, e7 * inv);
}

// ---------------- launch -----------------------------------------------------
extern "C" void kernel_launch(void* const* d_in, const int* in_sizes, int n_in,
                              void* d_out, int out_size)
{
    const float* X    = (const float*)d_in[0];
    const float* mask = (const float*)d_in[1];
    const float* Wk   = (const float*)d_in[2];
    const float* Wq   = (const float*)d_in[3];
    const float* Wv   = (const float*)d_in[4];
    const float* Wo   = (const float*)d_in[5];
    float* out = (float*)d_out;
    (void)in_sizes; (void)n_in; (void)out_size;

    // 1. Q,K projections (one pass over X)
    qk_gemm<<<dim3(2, M_ / 128), 256>>>(X, Wq, Wk);
    // 2. global K max over T
    kmax_part<<<dim3(B_, MX_CH), 128>>>();
    kmax_red<<<1, 512>>>();
    // 3. Ke = exp(K-max)*m^2 and Ksum partials
    ke_kern<<<dim3(KE_CH, B_), 256>>>(mask);
    ks_red<<<1, 512>>>();
    // 4. softmax(Q)
    softmax_q<<<(M_ * H_) / 256, 256>>>();
    // 5. S = Ke^T @ X (split-K)
    s_gemm<<<dim3(D_ / 128, S_CH, B_), 256>>>(X);
    // 6. Kvn = (S @ Wv per-head) / Ksum
    kv_small<<<B_ * H_, 512>>>(Wv);
    // 7. Wcomb = BlockDiag(Kvn) @ Wo
    wcomb_kern<<<dim3(B_, D_ / 128), 256>>>(Wo);
    // 8. out = Qs @ Wcomb[b]
    out_gemm<<<dim3(D_ / 128, M_ / 128), 256>>>(out);
}